// round 15
// baseline (speedup 1.0000x reference)
#include <cuda_runtime.h>
#include <cuda_fp16.h>
#include <math.h>
#include <stdint.h>

// ---------------- problem constants ----------------
#define T_TOK   4096
#define D_IN    4096
#define D_OUT   4096
#define N_EXP   8
#define RANK    16
#define SCALING 2.0f
#define NJ      (N_EXP + N_EXP*RANK)   // 136

// ---------------- mega GEMM tiling (proven R4/R8 config) ----------------
#define TILE_M  128
#define TILE_N  128
#define KC      64
#define NCHUNK_BASE (D_IN / KC)        // 64
#define NCHUNK  (NCHUNK_BASE + 2)

#define A_BYTES (TILE_M * 128)
#define B_BYTES (TILE_N * 128)
#define STAGE_BYTES (A_BYTES + B_BYTES)
#define NSTAGE  2

// ---------------- gate GEMM (N=136) ----------------
#define GN      136
#define GA_BYTES (128 * 128)
#define GB_BYTES (GN * 128)
#define GSTAGE_BYTES (GA_BYTES + GB_BYTES)
#define NSPLIT  4
#define GCHUNKS (NCHUNK_BASE / NSPLIT)

// ---------------- device scratch ----------------
__device__ __half g_xh[(size_t)T_TOK * D_IN];
__device__ __half g_wh[(size_t)D_OUT * D_IN];
__device__ __half g_W2[(size_t)NJ * D_IN];
__device__ __half g_L [(size_t)D_OUT * 128];
__device__ __half g_C [(size_t)T_TOK * 128];
__device__ float  g_part[(size_t)NSPLIT * T_TOK * NJ];

// ---------------- helpers ----------------
__device__ __forceinline__ uint32_t smem_u32(const void* p) {
    uint32_t a;
    asm("{ .reg .u64 t; cvta.to.shared.u64 t, %1; cvt.u32.u64 %0, t; }" : "=r"(a) : "l"(p));
    return a;
}
__device__ __forceinline__ void cp16(uint32_t dst, const void* src) {
    asm volatile("cp.async.cg.shared.global [%0], [%1], 16;" :: "r"(dst), "l"(src));
}
__device__ __forceinline__ void cp_commit() { asm volatile("cp.async.commit_group;" ::: "memory"); }
__device__ __forceinline__ void cp_wait1()  { asm volatile("cp.async.wait_group 1;" ::: "memory"); }
__device__ __forceinline__ void cp_wait0()  { asm volatile("cp.async.wait_group 0;" ::: "memory"); }

__device__ __forceinline__ void ldsm_x4(uint32_t (&r)[4], uint32_t addr) {
    asm volatile("ldmatrix.sync.aligned.m8n8.x4.shared.b16 {%0,%1,%2,%3}, [%4];"
                 : "=r"(r[0]), "=r"(r[1]), "=r"(r[2]), "=r"(r[3]) : "r"(addr));
}
__device__ __forceinline__ void ldsm_x2(uint32_t (&r)[2], uint32_t addr) {
    asm volatile("ldmatrix.sync.aligned.m8n8.x2.shared.b16 {%0,%1}, [%2];"
                 : "=r"(r[0]), "=r"(r[1]) : "r"(addr));
}
__device__ __forceinline__ void mma16816(float (&d)[4], const uint32_t (&a)[4], const uint32_t b0, const uint32_t b1) {
    asm volatile(
        "mma.sync.aligned.m16n8k16.row.col.f32.f16.f16.f32 "
        "{%0,%1,%2,%3},{%4,%5,%6,%7},{%8,%9},{%0,%1,%2,%3};"
        : "+f"(d[0]), "+f"(d[1]), "+f"(d[2]), "+f"(d[3])
        : "r"(a[0]), "r"(a[1]), "r"(a[2]), "r"(a[3]), "r"(b0), "r"(b1));
}

// ---------------- convert f32 -> fp16 ----------------
__global__ __launch_bounds__(256) void tohalf_kernel(
    const float* __restrict__ src, __half* __restrict__ dst, int n4)
{
    int i = blockIdx.x * 256 + threadIdx.x;
    if (i >= n4) return;
    float4 v = ((const float4*)src)[i];
    ((__half2*)dst)[i * 2]     = __floats2half2_rn(v.x, v.y);
    ((__half2*)dst)[i * 2 + 1] = __floats2half2_rn(v.z, v.w);
}

// ---------------- merged pack: W2[136][4096] and L[o][128] ----------------
#define W2_ELEMS (NJ * D_IN)        // 557056
#define L_ELEMS  (D_OUT * 128)      // 524288
__global__ __launch_bounds__(256) void pack_all_kernel(
    const float* __restrict__ gate_w, const float* __restrict__ lora_A,
    const float* __restrict__ lora_B)
{
    int idx = blockIdx.x * 256 + threadIdx.x;
    if (idx < W2_ELEMS) {
        int row = idx / D_IN, d = idx % D_IN;
        float v = (row < N_EXP) ? gate_w[(size_t)row * D_IN + d]
                                : lora_A[(size_t)(row - N_EXP) * D_IN + d];
        g_W2[idx] = __float2half(v);
    } else {
        int i2 = idx - W2_ELEMS;
        if (i2 < L_ELEMS) {
            int o = i2 >> 7, j = i2 & 127;
            int e = j >> 4, r = j & 15;
            g_L[i2] = __float2half(lora_B[((size_t)e * D_OUT + o) * RANK + r]);
        }
    }
}

// ---------------- kernel G1: gate/low GEMM, 512 threads, N split across warp groups ----------------
__global__ __launch_bounds__(512, 1) void gate_gemm_kernel()
{
    extern __shared__ __align__(1024) char dsm[];
    const int tid = threadIdx.x;
    const int wid = tid >> 5;
    const int lane = tid & 31;
    const int mwarp = wid & 7;          // M-row slice (16 rows)
    const int grp  = wid >> 3;          // 0: N-tiles 0..8, 1: N-tiles 9..16
    const int split = blockIdx.x;
    const int bt = blockIdx.y * 128;
    const int k0 = split * GCHUNKS;

    const uint32_t smb = smem_u32(dsm);

    // group 0 handles 9 tiles, group 1 handles 8
    const int NT = grp ? 8 : 9;
    float acc[9][4];
#pragma unroll
    for (int i = 0; i < 9; i++)
#pragma unroll
        for (int q = 0; q < 4; q++) acc[i][q] = 0.f;

    auto load_chunk = [&](int kk, int s) {
        const uint32_t sb = smb + s * GSTAGE_BYTES;
        const __half* Asrc = g_xh + (size_t)bt * D_IN + (k0 + kk) * KC;
        const __half* Bsrc = g_W2 + (size_t)(k0 + kk) * KC;
        // A: 128 rows x 8 granules = 1024
#pragma unroll
        for (int it = 0; it < 2; it++) {
            int i = tid + it * 512;
            int row = i >> 3, g = i & 7;
            uint32_t off = (uint32_t)(row * 128) + ((uint32_t)(g ^ (row & 7)) << 4);
            cp16(sb + off, Asrc + (size_t)row * D_IN + g * 8);
        }
        // B: 136 rows x 8 granules = 1088
#pragma unroll
        for (int it = 0; it < 3; it++) {
            int i = tid + it * 512;
            if (i < GN * 8) {
                int row = i >> 3, g = i & 7;
                uint32_t off = (uint32_t)(row * 128) + ((uint32_t)(g ^ (row & 7)) << 4);
                cp16(sb + GA_BYTES + off, Bsrc + (size_t)row * D_IN + g * 8);
            }
        }
        cp_commit();
    };

    load_chunk(0, 0);

    for (int kk = 0; kk < GCHUNKS; kk++) {
        const int s = kk & 1;
        if (kk + 1 < GCHUNKS) { load_chunk(kk + 1, s ^ 1); cp_wait1(); }
        else                  { cp_wait0(); }
        __syncthreads();

        const uint32_t sA = smb + s * GSTAGE_BYTES;
        const uint32_t sB = sA + GA_BYTES;

#pragma unroll
        for (int ks = 0; ks < 4; ks++) {
            uint32_t a[4];
            {
                int row = mwarp * 16 + (lane & 15);
                int chunk = ks * 2 + (lane >> 4);
                ldsm_x4(a, sA + (uint32_t)(row * 128) + ((uint32_t)(chunk ^ (row & 7)) << 4));
            }
            uint32_t b[9][2];
            if (grp == 0) {
                // tiles 0..7 via 4 x4 loads (rows 0..63), tile 8 via x2 (rows 64..71)
#pragma unroll
                for (int pr = 0; pr < 4; pr++) {
                    int nrow = pr * 16 + (lane & 7) + ((lane >> 4) << 3);
                    int chunk = ks * 2 + ((lane >> 3) & 1);
                    uint32_t r4[4];
                    ldsm_x4(r4, sB + (uint32_t)(nrow * 128) + ((uint32_t)(chunk ^ (nrow & 7)) << 4));
                    b[pr * 2 + 0][0] = r4[0]; b[pr * 2 + 0][1] = r4[1];
                    b[pr * 2 + 1][0] = r4[2]; b[pr * 2 + 1][1] = r4[3];
                }
                {
                    int nrow = 64 + (lane & 7);
                    int chunk = ks * 2 + ((lane >> 3) & 1);
                    uint32_t r2[2];
                    ldsm_x2(r2, sB + (uint32_t)(nrow * 128) + ((uint32_t)(chunk ^ (nrow & 7)) << 4));
                    b[8][0] = r2[0]; b[8][1] = r2[1];
                }
            } else {
                // tile 9 via x2 (rows 72..79), tiles 10..15 via 3 x4 loads (rows 80..127),
                // tile 16 via x2 (rows 128..135)
                {
                    int nrow = 72 + (lane & 7);
                    int chunk = ks * 2 + ((lane >> 3) & 1);
                    uint32_t r2[2];
                    ldsm_x2(r2, sB + (uint32_t)(nrow * 128) + ((uint32_t)(chunk ^ (nrow & 7)) << 4));
                    b[0][0] = r2[0]; b[0][1] = r2[1];
                }
#pragma unroll
                for (int pr = 0; pr < 3; pr++) {
                    int nrow = 80 + pr * 16 + (lane & 7) + ((lane >> 4) << 3);
                    int chunk = ks * 2 + ((lane >> 3) & 1);
                    uint32_t r4[4];
                    ldsm_x4(r4, sB + (uint32_t)(nrow * 128) + ((uint32_t)(chunk ^ (nrow & 7)) << 4));
                    b[1 + pr * 2 + 0][0] = r4[0]; b[1 + pr * 2 + 0][1] = r4[1];
                    b[1 + pr * 2 + 1][0] = r4[2]; b[1 + pr * 2 + 1][1] = r4[3];
                }
                {
                    int nrow = 128 + (lane & 7);
                    int chunk = ks * 2 + ((lane >> 3) & 1);
                    uint32_t r2[2];
                    ldsm_x2(r2, sB + (uint32_t)(nrow * 128) + ((uint32_t)(chunk ^ (nrow & 7)) << 4));
                    b[7][0] = r2[0]; b[7][1] = r2[1];
                }
            }
#pragma unroll
            for (int ni = 0; ni < 9; ni++)
                if (ni < NT)
                    mma16816(acc[ni], a, b[ni][0], b[ni][1]);
        }
        __syncthreads();
    }

    // epilogue -> g_part[split][t][136]; grp0 cols 0..71, grp1 cols 72..135
    const int gq = lane >> 2;
    const int cq = (lane & 3) * 2;
    const int r0 = bt + mwarp * 16 + gq;
    const int nbase = grp ? 72 : 0;
    float* p0 = g_part + ((size_t)split * T_TOK + r0) * NJ + nbase;
    float* p1 = g_part + ((size_t)split * T_TOK + r0 + 8) * NJ + nbase;
#pragma unroll
    for (int ni = 0; ni < 9; ni++) {
        if (ni < NT) {
            int c0 = ni * 8 + cq;
            *(float2*)(p0 + c0) = make_float2(acc[ni][0], acc[ni][1]);
            *(float2*)(p1 + c0) = make_float2(acc[ni][2], acc[ni][3]);
        }
    }
}

// ---------------- kernel G2: reduce + top-2 softmax -> C[t,128] ----------------
__global__ __launch_bounds__(NJ) void route_kernel()
{
    __shared__ float lg[NJ];
    __shared__ float s_w[2];
    __shared__ int   s_i[2];
    const int t = blockIdx.x;
    const int j = threadIdx.x;

    float v = 0.f;
#pragma unroll
    for (int s = 0; s < NSPLIT; s++)
        v += g_part[((size_t)s * T_TOK + t) * NJ + j];
    lg[j] = v;
    __syncthreads();

    if (j == 0) {
        int i0 = 0; float v0 = lg[0];
#pragma unroll
        for (int e = 1; e < N_EXP; e++) { float w = lg[e]; if (w > v0) { v0 = w; i0 = e; } }
        int i1 = -1; float v1 = -INFINITY;
#pragma unroll
        for (int e = 0; e < N_EXP; e++) {
            if (e == i0) continue;
            float w = lg[e];
            if (w > v1) { v1 = w; i1 = e; }
        }
        float e1 = expf(v1 - v0);
        float w0 = 1.f / (1.f + e1);
        s_w[0] = SCALING * w0;
        s_w[1] = SCALING * e1 * w0;
        s_i[0] = i0; s_i[1] = i1;
    }
    __syncthreads();

    if (j < 128) {
        int e = j >> 4;
        float w = (e == s_i[0]) ? s_w[0] : (e == s_i[1]) ? s_w[1] : 0.f;
        g_C[(size_t)t * 128 + j] = __float2half(w * lg[N_EXP + j]);
    }
}

// ---------------- kernel 3: fused HMMA GEMM (R8 proven, unchanged) ----------------
__global__ __launch_bounds__(256, 2) void mega_gemm_kernel(
    const float* __restrict__ bias, float* __restrict__ out)
{
    extern __shared__ __align__(1024) char dsm[];
    __shared__ float s_bias[TILE_N];

    const int tid = threadIdx.x;
    const int wid = tid >> 5;
    const int lane = tid & 31;
    const int wm = wid >> 2;
    const int wn = wid & 3;
    const int bo = blockIdx.x * TILE_N;
    const int bt = blockIdx.y * TILE_M;

    const uint32_t smb = smem_u32(dsm);
    if (tid < TILE_N) s_bias[tid] = bias[bo + tid];

    float acc[4][4][4];
#pragma unroll
    for (int i = 0; i < 4; i++)
#pragma unroll
        for (int j = 0; j < 4; j++)
#pragma unroll
            for (int q = 0; q < 4; q++) acc[i][j][q] = 0.f;

    auto load_chunk = [&](int k, int s) {
        const uint32_t sb = smb + s * STAGE_BYTES;
        const __half *Asrc, *Bsrc;
        size_t astr, bstr;
        if (k < NCHUNK_BASE) {
            Asrc = g_xh + (size_t)bt * D_IN + k * KC;
            Bsrc = g_wh + (size_t)bo * D_IN + k * KC;
            astr = D_IN; bstr = D_IN;
        } else {
            int kc = k - NCHUNK_BASE;
            Asrc = g_C + (size_t)bt * 128 + kc * KC;
            Bsrc = g_L + (size_t)bo * 128 + kc * KC;
            astr = 128; bstr = 128;
        }
#pragma unroll
        for (int it = 0; it < 4; it++) {
            int i = tid + it * 256;
            int row = i >> 3, g = i & 7;
            uint32_t off = (uint32_t)(row * 128) + ((uint32_t)(g ^ (row & 7)) << 4);
            cp16(sb + off, Asrc + (size_t)row * astr + g * 8);
            cp16(sb + A_BYTES + off, Bsrc + (size_t)row * bstr + g * 8);
        }
        cp_commit();
    };

    load_chunk(0, 0);

    for (int k = 0; k < NCHUNK; k++) {
        const int s = k & 1;
        if (k + 1 < NCHUNK) { load_chunk(k + 1, s ^ 1); cp_wait1(); }
        else                { cp_wait0(); }
        __syncthreads();

        const uint32_t sA = smb + s * STAGE_BYTES;
        const uint32_t sB = sA + A_BYTES;

#pragma unroll
        for (int ks = 0; ks < 4; ks++) {
            uint32_t a[4][4];
#pragma unroll
            for (int mi = 0; mi < 4; mi++) {
                int row = wm * 64 + mi * 16 + (lane & 15);
                int chunk = ks * 2 + (lane >> 4);
                ldsm_x4(a[mi], sA + (uint32_t)(row * 128) + ((uint32_t)(chunk ^ (row & 7)) << 4));
            }
            uint32_t b[4][2];
#pragma unroll
            for (int pr = 0; pr < 2; pr++) {
                int nrow = wn * 32 + pr * 16 + (lane & 7) + ((lane >> 4) << 3);
                int chunk = ks * 2 + ((lane >> 3) & 1);
                uint32_t r4[4];
                ldsm_x4(r4, sB + (uint32_t)(nrow * 128) + ((uint32_t)(chunk ^ (nrow & 7)) << 4));
                b[pr * 2 + 0][0] = r4[0]; b[pr * 2 + 0][1] = r4[1];
                b[pr * 2 + 1][0] = r4[2]; b[pr * 2 + 1][1] = r4[3];
            }
#pragma unroll
            for (int mi = 0; mi < 4; mi++)
#pragma unroll
                for (int ni = 0; ni < 4; ni++)
                    mma16816(acc[mi][ni], a[mi], b[ni][0], b[ni][1]);
        }
        __syncthreads();
    }

    const int gq = lane >> 2;
    const int cq = (lane & 3) * 2;
#pragma unroll
    for (int mi = 0; mi < 4; mi++) {
        int r0 = bt + wm * 64 + mi * 16 + gq;
#pragma unroll
        for (int ni = 0; ni < 4; ni++) {
            int c0 = bo + wn * 32 + ni * 8 + cq;
            float bx = s_bias[c0 - bo], by = s_bias[c0 - bo + 1];
            *(float2*)(out + (size_t)r0 * D_OUT + c0)       = make_float2(acc[mi][ni][0] + bx, acc[mi][ni][1] + by);
            *(float2*)(out + (size_t)(r0 + 8) * D_OUT + c0) = make_float2(acc[mi][ni][2] + bx, acc[mi][ni][3] + by);
        }
    }
}

// ---------------- launch ----------------
extern "C" void kernel_launch(void* const* d_in, const int* in_sizes, int n_in,
                              void* d_out, int out_size)
{
    const float* x      = (const float*)d_in[0];
    const float* gate_w = (const float*)d_in[1];
    const float* base_w = (const float*)d_in[2];
    const float* base_b = (const float*)d_in[3];
    const float* lora_A = (const float*)d_in[4];
    const float* lora_B = (const float*)d_in[5];
    float* out = (float*)d_out;

    static cudaStream_t s1 = nullptr, s2 = nullptr;
    static cudaEvent_t e0 = nullptr, eP = nullptr, eW = nullptr;
    if (s1 == nullptr) {
        cudaStreamCreateWithFlags(&s1, cudaStreamNonBlocking);
        cudaStreamCreateWithFlags(&s2, cudaStreamNonBlocking);
        cudaEventCreateWithFlags(&e0, cudaEventDisableTiming);
        cudaEventCreateWithFlags(&eP, cudaEventDisableTiming);
        cudaEventCreateWithFlags(&eW, cudaEventDisableTiming);
        cudaFuncSetAttribute(mega_gemm_kernel, cudaFuncAttributeMaxDynamicSharedMemorySize,
                             NSTAGE * STAGE_BYTES);
        cudaFuncSetAttribute(gate_gemm_kernel, cudaFuncAttributeMaxDynamicSharedMemorySize,
                             2 * GSTAGE_BYTES);
    }

    __half *xh, *wh;
    cudaGetSymbolAddress((void**)&xh, g_xh);
    cudaGetSymbolAddress((void**)&wh, g_wh);

    // fork
    cudaEventRecord(e0, 0);
    cudaStreamWaitEvent(s1, e0, 0);
    cudaStreamWaitEvent(s2, e0, 0);

    // s0: tohalf(x) -> gate chain
    const int n4x = (T_TOK * D_IN) / 4;
    tohalf_kernel<<<(n4x + 255) / 256, 256>>>(x, xh, n4x);

    // s1: tohalf(w) (mega weight input)
    const int n4w = (D_OUT * D_IN) / 4;
    tohalf_kernel<<<(n4w + 255) / 256, 256, 0, s1>>>(base_w, wh, n4w);
    cudaEventRecord(eW, s1);

    // s2: merged packs (W2 + L), independent of conversions
    const int packn = W2_ELEMS + L_ELEMS;
    pack_all_kernel<<<(packn + 255) / 256, 256, 0, s2>>>(gate_w, lora_A, lora_B);
    cudaEventRecord(eP, s2);

    // s0: gate chain after tohalf(x) + packs
    cudaStreamWaitEvent(0, eP, 0);
    gate_gemm_kernel<<<dim3(NSPLIT, T_TOK / 128), 512, 2 * GSTAGE_BYTES>>>();
    route_kernel<<<T_TOK, NJ>>>();

    // s0: join tohalf(w), then fused mega
    cudaStreamWaitEvent(0, eW, 0);
    mega_gemm_kernel<<<dim3(D_OUT / TILE_N, T_TOK / TILE_M), 256, NSTAGE * STAGE_BYTES>>>(base_b, out);
}

// round 16
// speedup vs baseline: 1.0066x; 1.0066x over previous
#include <cuda_runtime.h>
#include <cuda_fp16.h>
#include <math.h>
#include <stdint.h>

// ---------------- problem constants ----------------
#define T_TOK   4096
#define D_IN    4096
#define D_OUT   4096
#define N_EXP   8
#define RANK    16
#define SCALING 2.0f
#define NJ      (N_EXP + N_EXP*RANK)   // 136

// ---------------- mega GEMM tiling (proven R4/R8 config) ----------------
#define TILE_M  128
#define TILE_N  128
#define KC      64
#define NCHUNK_BASE (D_IN / KC)        // 64
#define NCHUNK  (NCHUNK_BASE + 2)

#define A_BYTES (TILE_M * 128)
#define B_BYTES (TILE_N * 128)
#define STAGE_BYTES (A_BYTES + B_BYTES)
#define NSTAGE  2

// ---------------- gate GEMM (N=136 split over 2 CTAs: 72 + 64 rows) ----------------
#define GA_BYTES (128 * 128)           // 16 KB A tile
#define GB_ROWS  72                    // max B rows per CTA (z=0: 72, z=1: 64)
#define GB_BYTES (GB_ROWS * 128)       // 9216
#define GSTAGE_BYTES (GA_BYTES + GB_BYTES) // 25600
#define NSPLIT  4
#define GCHUNKS (NCHUNK_BASE / NSPLIT)

// ---------------- device scratch ----------------
__device__ __half g_xh[(size_t)T_TOK * D_IN];
__device__ __half g_wh[(size_t)D_OUT * D_IN];
__device__ __half g_W2[(size_t)NJ * D_IN];
__device__ __half g_L [(size_t)D_OUT * 128];
__device__ __half g_C [(size_t)T_TOK * 128];
__device__ float  g_part[(size_t)NSPLIT * T_TOK * NJ];

// ---------------- helpers ----------------
__device__ __forceinline__ uint32_t smem_u32(const void* p) {
    uint32_t a;
    asm("{ .reg .u64 t; cvta.to.shared.u64 t, %1; cvt.u32.u64 %0, t; }" : "=r"(a) : "l"(p));
    return a;
}
__device__ __forceinline__ void cp16(uint32_t dst, const void* src) {
    asm volatile("cp.async.cg.shared.global [%0], [%1], 16;" :: "r"(dst), "l"(src));
}
__device__ __forceinline__ void cp_commit() { asm volatile("cp.async.commit_group;" ::: "memory"); }
__device__ __forceinline__ void cp_wait1()  { asm volatile("cp.async.wait_group 1;" ::: "memory"); }
__device__ __forceinline__ void cp_wait0()  { asm volatile("cp.async.wait_group 0;" ::: "memory"); }

__device__ __forceinline__ void ldsm_x4(uint32_t (&r)[4], uint32_t addr) {
    asm volatile("ldmatrix.sync.aligned.m8n8.x4.shared.b16 {%0,%1,%2,%3}, [%4];"
                 : "=r"(r[0]), "=r"(r[1]), "=r"(r[2]), "=r"(r[3]) : "r"(addr));
}
__device__ __forceinline__ void ldsm_x2(uint32_t (&r)[2], uint32_t addr) {
    asm volatile("ldmatrix.sync.aligned.m8n8.x2.shared.b16 {%0,%1}, [%2];"
                 : "=r"(r[0]), "=r"(r[1]) : "r"(addr));
}
__device__ __forceinline__ void mma16816(float (&d)[4], const uint32_t (&a)[4], const uint32_t b0, const uint32_t b1) {
    asm volatile(
        "mma.sync.aligned.m16n8k16.row.col.f32.f16.f16.f32 "
        "{%0,%1,%2,%3},{%4,%5,%6,%7},{%8,%9},{%0,%1,%2,%3};"
        : "+f"(d[0]), "+f"(d[1]), "+f"(d[2]), "+f"(d[3])
        : "r"(a[0]), "r"(a[1]), "r"(a[2]), "r"(a[3]), "r"(b0), "r"(b1));
}

// ---------------- convert f32 -> fp16 ----------------
__global__ __launch_bounds__(256) void tohalf_kernel(
    const float* __restrict__ src, __half* __restrict__ dst, int n4)
{
    int i = blockIdx.x * 256 + threadIdx.x;
    if (i >= n4) return;
    float4 v = ((const float4*)src)[i];
    ((__half2*)dst)[i * 2]     = __floats2half2_rn(v.x, v.y);
    ((__half2*)dst)[i * 2 + 1] = __floats2half2_rn(v.z, v.w);
}

// ---------------- merged pack: W2[136][4096] and L[o][128] ----------------
#define W2_ELEMS (NJ * D_IN)        // 557056
#define L_ELEMS  (D_OUT * 128)      // 524288
__global__ __launch_bounds__(256) void pack_all_kernel(
    const float* __restrict__ gate_w, const float* __restrict__ lora_A,
    const float* __restrict__ lora_B)
{
    int idx = blockIdx.x * 256 + threadIdx.x;
    if (idx < W2_ELEMS) {
        int row = idx / D_IN, d = idx % D_IN;
        float v = (row < N_EXP) ? gate_w[(size_t)row * D_IN + d]
                                : lora_A[(size_t)(row - N_EXP) * D_IN + d];
        g_W2[idx] = __float2half(v);
    } else {
        int i2 = idx - W2_ELEMS;
        if (i2 < L_ELEMS) {
            int o = i2 >> 7, j = i2 & 127;
            int e = j >> 4, r = j & 15;
            g_L[i2] = __float2half(lora_B[((size_t)e * D_OUT + o) * RANK + r]);
        }
    }
}

// ---------------- kernel G1: gate/low GEMM, N split across blockIdx.z ----------------
// z=0: N rows 0..71 (9 n8-tiles), z=1: N rows 72..135 (8 n8-tiles)
__global__ __launch_bounds__(256, 2) void gate_gemm_kernel()
{
    extern __shared__ __align__(1024) char dsm[];
    const int tid = threadIdx.x;
    const int wid = tid >> 5;
    const int lane = tid & 31;
    const int split = blockIdx.x;
    const int bt = blockIdx.y * 128;
    const int zh = blockIdx.z;          // 0 or 1
    const int k0 = split * GCHUNKS;
    const int nbase = zh ? 72 : 0;      // global N-row base
    const int nrows = zh ? 64 : 72;     // B rows this CTA
    const int NT    = zh ? 8 : 9;       // n8 tiles this CTA

    const uint32_t smb = smem_u32(dsm);

    float acc[9][4];
#pragma unroll
    for (int i = 0; i < 9; i++)
#pragma unroll
        for (int q = 0; q < 4; q++) acc[i][q] = 0.f;

    auto load_chunk = [&](int kk, int s) {
        const uint32_t sb = smb + s * GSTAGE_BYTES;
        const __half* Asrc = g_xh + (size_t)bt * D_IN + (k0 + kk) * KC;
        const __half* Bsrc = g_W2 + (size_t)nbase * D_IN + (k0 + kk) * KC;
        // A: 128 rows x 8 granules = 1024
#pragma unroll
        for (int it = 0; it < 4; it++) {
            int i = tid + it * 256;
            int row = i >> 3, g = i & 7;
            uint32_t off = (uint32_t)(row * 128) + ((uint32_t)(g ^ (row & 7)) << 4);
            cp16(sb + off, Asrc + (size_t)row * D_IN + g * 8);
        }
        // B: nrows x 8 granules (<= 576)
        const int bgr = nrows * 8;
#pragma unroll
        for (int it = 0; it < 3; it++) {
            int i = tid + it * 256;
            if (i < bgr) {
                int row = i >> 3, g = i & 7;
                uint32_t off = (uint32_t)(row * 128) + ((uint32_t)(g ^ (row & 7)) << 4);
                cp16(sb + GA_BYTES + off, Bsrc + (size_t)row * D_IN + g * 8);
            }
        }
        cp_commit();
    };

    load_chunk(0, 0);

    for (int kk = 0; kk < GCHUNKS; kk++) {
        const int s = kk & 1;
        if (kk + 1 < GCHUNKS) { load_chunk(kk + 1, s ^ 1); cp_wait1(); }
        else                  { cp_wait0(); }
        __syncthreads();

        const uint32_t sA = smb + s * GSTAGE_BYTES;
        const uint32_t sB = sA + GA_BYTES;

#pragma unroll
        for (int ks = 0; ks < 4; ks++) {
            uint32_t a[4];
            {
                int row = wid * 16 + (lane & 15);
                int chunk = ks * 2 + (lane >> 4);
                ldsm_x4(a, sA + (uint32_t)(row * 128) + ((uint32_t)(chunk ^ (row & 7)) << 4));
            }
            uint32_t b[9][2];
            // 4 x4 loads covering local rows 0..63 (tiles 0..7)
#pragma unroll
            for (int pr = 0; pr < 4; pr++) {
                int nrow = pr * 16 + (lane & 7) + ((lane >> 4) << 3);
                int chunk = ks * 2 + ((lane >> 3) & 1);
                uint32_t r4[4];
                ldsm_x4(r4, sB + (uint32_t)(nrow * 128) + ((uint32_t)(chunk ^ (nrow & 7)) << 4));
                b[pr * 2 + 0][0] = r4[0]; b[pr * 2 + 0][1] = r4[1];
                b[pr * 2 + 1][0] = r4[2]; b[pr * 2 + 1][1] = r4[3];
            }
            if (NT == 9) {
                // tile 8: local rows 64..71
                int nrow = 64 + (lane & 7);
                int chunk = ks * 2 + ((lane >> 3) & 1);
                uint32_t r2[2];
                ldsm_x2(r2, sB + (uint32_t)(nrow * 128) + ((uint32_t)(chunk ^ (nrow & 7)) << 4));
                b[8][0] = r2[0]; b[8][1] = r2[1];
            }
#pragma unroll
            for (int ni = 0; ni < 9; ni++)
                if (ni < NT)
                    mma16816(acc[ni], a, b[ni][0], b[ni][1]);
        }
        __syncthreads();
    }

    // epilogue -> g_part[split][t][nbase + 0..NT*8)
    const int gq = lane >> 2;
    const int cq = (lane & 3) * 2;
    const int r0 = bt + wid * 16 + gq;
    float* p0 = g_part + ((size_t)split * T_TOK + r0) * NJ + nbase;
    float* p1 = g_part + ((size_t)split * T_TOK + r0 + 8) * NJ + nbase;
#pragma unroll
    for (int ni = 0; ni < 9; ni++) {
        if (ni < NT) {
            int c0 = ni * 8 + cq;
            *(float2*)(p0 + c0) = make_float2(acc[ni][0], acc[ni][1]);
            *(float2*)(p1 + c0) = make_float2(acc[ni][2], acc[ni][3]);
        }
    }
}

// ---------------- kernel G2: reduce + top-2 softmax -> C[t,128] ----------------
__global__ __launch_bounds__(NJ) void route_kernel()
{
    __shared__ float lg[NJ];
    __shared__ float s_w[2];
    __shared__ int   s_i[2];
    const int t = blockIdx.x;
    const int j = threadIdx.x;

    float v = 0.f;
#pragma unroll
    for (int s = 0; s < NSPLIT; s++)
        v += g_part[((size_t)s * T_TOK + t) * NJ + j];
    lg[j] = v;
    __syncthreads();

    if (j == 0) {
        int i0 = 0; float v0 = lg[0];
#pragma unroll
        for (int e = 1; e < N_EXP; e++) { float w = lg[e]; if (w > v0) { v0 = w; i0 = e; } }
        int i1 = -1; float v1 = -INFINITY;
#pragma unroll
        for (int e = 0; e < N_EXP; e++) {
            if (e == i0) continue;
            float w = lg[e];
            if (w > v1) { v1 = w; i1 = e; }
        }
        float e1 = expf(v1 - v0);
        float w0 = 1.f / (1.f + e1);
        s_w[0] = SCALING * w0;
        s_w[1] = SCALING * e1 * w0;
        s_i[0] = i0; s_i[1] = i1;
    }
    __syncthreads();

    if (j < 128) {
        int e = j >> 4;
        float w = (e == s_i[0]) ? s_w[0] : (e == s_i[1]) ? s_w[1] : 0.f;
        g_C[(size_t)t * 128 + j] = __float2half(w * lg[N_EXP + j]);
    }
}

// ---------------- kernel 3: fused HMMA GEMM (R8 proven, unchanged) ----------------
__global__ __launch_bounds__(256, 2) void mega_gemm_kernel(
    const float* __restrict__ bias, float* __restrict__ out)
{
    extern __shared__ __align__(1024) char dsm[];
    __shared__ float s_bias[TILE_N];

    const int tid = threadIdx.x;
    const int wid = tid >> 5;
    const int lane = tid & 31;
    const int wm = wid >> 2;
    const int wn = wid & 3;
    const int bo = blockIdx.x * TILE_N;
    const int bt = blockIdx.y * TILE_M;

    const uint32_t smb = smem_u32(dsm);
    if (tid < TILE_N) s_bias[tid] = bias[bo + tid];

    float acc[4][4][4];
#pragma unroll
    for (int i = 0; i < 4; i++)
#pragma unroll
        for (int j = 0; j < 4; j++)
#pragma unroll
            for (int q = 0; q < 4; q++) acc[i][j][q] = 0.f;

    auto load_chunk = [&](int k, int s) {
        const uint32_t sb = smb + s * STAGE_BYTES;
        const __half *Asrc, *Bsrc;
        size_t astr, bstr;
        if (k < NCHUNK_BASE) {
            Asrc = g_xh + (size_t)bt * D_IN + k * KC;
            Bsrc = g_wh + (size_t)bo * D_IN + k * KC;
            astr = D_IN; bstr = D_IN;
        } else {
            int kc = k - NCHUNK_BASE;
            Asrc = g_C + (size_t)bt * 128 + kc * KC;
            Bsrc = g_L + (size_t)bo * 128 + kc * KC;
            astr = 128; bstr = 128;
        }
#pragma unroll
        for (int it = 0; it < 4; it++) {
            int i = tid + it * 256;
            int row = i >> 3, g = i & 7;
            uint32_t off = (uint32_t)(row * 128) + ((uint32_t)(g ^ (row & 7)) << 4);
            cp16(sb + off, Asrc + (size_t)row * astr + g * 8);
            cp16(sb + A_BYTES + off, Bsrc + (size_t)row * bstr + g * 8);
        }
        cp_commit();
    };

    load_chunk(0, 0);

    for (int k = 0; k < NCHUNK; k++) {
        const int s = k & 1;
        if (k + 1 < NCHUNK) { load_chunk(k + 1, s ^ 1); cp_wait1(); }
        else                { cp_wait0(); }
        __syncthreads();

        const uint32_t sA = smb + s * STAGE_BYTES;
        const uint32_t sB = sA + A_BYTES;

#pragma unroll
        for (int ks = 0; ks < 4; ks++) {
            uint32_t a[4][4];
#pragma unroll
            for (int mi = 0; mi < 4; mi++) {
                int row = wm * 64 + mi * 16 + (lane & 15);
                int chunk = ks * 2 + (lane >> 4);
                ldsm_x4(a[mi], sA + (uint32_t)(row * 128) + ((uint32_t)(chunk ^ (row & 7)) << 4));
            }
            uint32_t b[4][2];
#pragma unroll
            for (int pr = 0; pr < 2; pr++) {
                int nrow = wn * 32 + pr * 16 + (lane & 7) + ((lane >> 4) << 3);
                int chunk = ks * 2 + ((lane >> 3) & 1);
                uint32_t r4[4];
                ldsm_x4(r4, sB + (uint32_t)(nrow * 128) + ((uint32_t)(chunk ^ (nrow & 7)) << 4));
                b[pr * 2 + 0][0] = r4[0]; b[pr * 2 + 0][1] = r4[1];
                b[pr * 2 + 1][0] = r4[2]; b[pr * 2 + 1][1] = r4[3];
            }
#pragma unroll
            for (int mi = 0; mi < 4; mi++)
#pragma unroll
                for (int ni = 0; ni < 4; ni++)
                    mma16816(acc[mi][ni], a[mi], b[ni][0], b[ni][1]);
        }
        __syncthreads();
    }

    const int gq = lane >> 2;
    const int cq = (lane & 3) * 2;
#pragma unroll
    for (int mi = 0; mi < 4; mi++) {
        int r0 = bt + wm * 64 + mi * 16 + gq;
#pragma unroll
        for (int ni = 0; ni < 4; ni++) {
            int c0 = bo + wn * 32 + ni * 8 + cq;
            float bx = s_bias[c0 - bo], by = s_bias[c0 - bo + 1];
            *(float2*)(out + (size_t)r0 * D_OUT + c0)       = make_float2(acc[mi][ni][0] + bx, acc[mi][ni][1] + by);
            *(float2*)(out + (size_t)(r0 + 8) * D_OUT + c0) = make_float2(acc[mi][ni][2] + bx, acc[mi][ni][3] + by);
        }
    }
}

// ---------------- launch ----------------
extern "C" void kernel_launch(void* const* d_in, const int* in_sizes, int n_in,
                              void* d_out, int out_size)
{
    const float* x      = (const float*)d_in[0];
    const float* gate_w = (const float*)d_in[1];
    const float* base_w = (const float*)d_in[2];
    const float* base_b = (const float*)d_in[3];
    const float* lora_A = (const float*)d_in[4];
    const float* lora_B = (const float*)d_in[5];
    float* out = (float*)d_out;

    static cudaStream_t s1 = nullptr, s2 = nullptr;
    static cudaEvent_t e0 = nullptr, eP = nullptr, eW = nullptr;
    if (s1 == nullptr) {
        cudaStreamCreateWithFlags(&s1, cudaStreamNonBlocking);
        cudaStreamCreateWithFlags(&s2, cudaStreamNonBlocking);
        cudaEventCreateWithFlags(&e0, cudaEventDisableTiming);
        cudaEventCreateWithFlags(&eP, cudaEventDisableTiming);
        cudaEventCreateWithFlags(&eW, cudaEventDisableTiming);
        cudaFuncSetAttribute(mega_gemm_kernel, cudaFuncAttributeMaxDynamicSharedMemorySize,
                             NSTAGE * STAGE_BYTES);
        cudaFuncSetAttribute(gate_gemm_kernel, cudaFuncAttributeMaxDynamicSharedMemorySize,
                             2 * GSTAGE_BYTES);
    }

    __half *xh, *wh;
    cudaGetSymbolAddress((void**)&xh, g_xh);
    cudaGetSymbolAddress((void**)&wh, g_wh);

    // fork
    cudaEventRecord(e0, 0);
    cudaStreamWaitEvent(s1, e0, 0);
    cudaStreamWaitEvent(s2, e0, 0);

    // s0: tohalf(x) -> gate chain
    const int n4x = (T_TOK * D_IN) / 4;
    tohalf_kernel<<<(n4x + 255) / 256, 256>>>(x, xh, n4x);

    // s1: tohalf(w) (mega weight input)
    const int n4w = (D_OUT * D_IN) / 4;
    tohalf_kernel<<<(n4w + 255) / 256, 256, 0, s1>>>(base_w, wh, n4w);
    cudaEventRecord(eW, s1);

    // s2: merged packs (W2 + L), independent of conversions
    const int packn = W2_ELEMS + L_ELEMS;
    pack_all_kernel<<<(packn + 255) / 256, 256, 0, s2>>>(gate_w, lora_A, lora_B);
    cudaEventRecord(eP, s2);

    // s0: gate chain after tohalf(x) + packs
    cudaStreamWaitEvent(0, eP, 0);
    gate_gemm_kernel<<<dim3(NSPLIT, T_TOK / 128, 2), 256, 2 * GSTAGE_BYTES>>>();
    route_kernel<<<T_TOK, NJ>>>();

    // s0: join tohalf(w), then fused mega
    cudaStreamWaitEvent(0, eW, 0);
    mega_gemm_kernel<<<dim3(D_OUT / TILE_N, T_TOK / TILE_M), 256, NSTAGE * STAGE_BYTES>>>(base_b, out);
}